// round 15
// baseline (speedup 1.0000x reference)
#include <cuda_runtime.h>
#include <cuda_bf16.h>
#include <math.h>

#define BINS 30
#define P1T 128
#define MAX_ROWS 8192

// Global scratch: per-(bin,row) BCE sums (bin-major) + global bin counts.
// g_cnt is zero at module load; zero_cnt_kernel re-zeroes it at the END of
// each call so every graph replay starts from zero.
__device__ float        g_S[BINS * MAX_ROWS];
__device__ unsigned int g_cnt[BINS];

__global__ void zero_cnt_kernel() {
    if (threadIdx.x < BINS) g_cnt[threadIdx.x] = 0u;
}

// ---------------------------------------------------------------------------
// Pass 1: one block per row, single read of logits+target.
//  - hybrid fast/exact binning (validated rel_err 6.2e-6): fast EX2/RCP
//    sigmoid; elements within 1e-3 bin-units of an edge are recomputed with
//    the exact reference sequence. The exact fix-up is ONE guarded block per
//    8-element batch (bitmask), not 8 per-element branches.
//  - bce sums: TWO per-thread float histograms (4-link chains each).
//  - counts: TWO per-thread u8 histograms (4-link chains, 3 instr/elem) —
//    replaces the packed-register counters (~17 ALU instr/elem in R14).
//  - slot index b*128+tid shared by float and u8 arrays (no extra addressing).
// ---------------------------------------------------------------------------
__global__ void __launch_bounds__(P1T)
pass1_kernel(const float4* __restrict__ logits,
             const int4*  __restrict__ target,
             int rows, int c4)
{
    __shared__ float         s_a [BINS * P1T];   // 15360 B
    __shared__ float         s_b [BINS * P1T];   // 15360 B
    __shared__ unsigned char s_ca[BINS * P1T];   //  3840 B
    __shared__ unsigned char s_cb[BINS * P1T];   //  3840 B

    const int tid = threadIdx.x;

    #pragma unroll
    for (int b = 0; b < BINS; b++) {
        s_a [b * P1T + tid] = 0.0f;
        s_b [b * P1T + tid] = 0.0f;
        s_ca[b * P1T + tid] = 0;
        s_cb[b * P1T + tid] = 0;
    }
    // own columns only -> no sync needed before hot loop

    const int row = blockIdx.x;
    const float4* lrow = logits + (size_t)row * c4;
    const int4*   trow = target + (size_t)row * c4;

    const float DELTA = 1e-3f;

    int i = tid;
    if (i + P1T < c4) {
        float4 x0 = lrow[i];
        float4 x1 = lrow[i + P1T];
        int4   t0 = trow[i];
        int4   t1 = trow[i + P1T];

        for (;;) {
            const int inext = i + 2 * P1T;
            const bool more = (inext + P1T < c4);

            float4 xn0, xn1; int4 tn0, tn1;
            if (more) {                       // prefetch next batch first
                xn0 = lrow[inext];
                xn1 = lrow[inext + P1T];
                tn0 = trow[inext];
                tn1 = trow[inext + P1T];
            }

            float xv[8] = {x0.x, x0.y, x0.z, x0.w, x1.x, x1.y, x1.z, x1.w};
            int   tv[8] = {t0.x, t0.y, t0.z, t0.w, t1.x, t1.y, t1.z, t1.w};

            int      bb[8];
            float    bc[8];
            unsigned need = 0;

            #pragma unroll
            for (int k = 0; k < 8; k++) {
                float e  = __expf(-xv[k]);           // FMUL + MUFU.EX2
                float w1 = 1.0f + e;
                float s  = __fdividef(1.0f, w1);     // MUFU.RCP
                float g  = tv[k] ? (1.0f - s) : s;
                float gb = g * 29.9999f;
                int   b  = (int)gb;
                float fr = gb - (float)b;
                need |= (fr < DELTA || fr > 1.0f - DELTA) ? (1u << k) : 0u;
                bb[k] = b;
                bc[k] = (tv[k] ? 0.0f : xv[k]) + __logf(w1);
            }

            if (need) {            // rare exact fix-up, one guard per batch
                #pragma unroll
                for (int k = 0; k < 8; k++) {
                    if ((need >> k) & 1u) {
                        float ea  = expf(-xv[k]);
                        float w1a = 1.0f + ea;
                        float sa  = 1.0f / w1a;      // IEEE division
                        float ga  = tv[k] ? (1.0f - sa) : sa;
                        bb[k] = (int)(ga * 29.9999f);
                    }
                }
            }
            #pragma unroll
            for (int k = 0; k < 8; k++) {
                int b = bb[k];
                bb[k] = (b < 0 ? 0 : (b > BINS - 1 ? BINS - 1 : b)) * P1T + tid;
            }

            // two independent 4-link float chains
            #pragma unroll
            for (int k = 0; k < 4; k++) s_a[bb[k]] += bc[k];
            #pragma unroll
            for (int k = 4; k < 8; k++) s_b[bb[k]] += bc[k];
            // two independent 4-link u8 count chains
            #pragma unroll
            for (int k = 0; k < 4; k++) s_ca[bb[k]] += 1;
            #pragma unroll
            for (int k = 4; k < 8; k++) s_cb[bb[k]] += 1;

            if (!more) { i = inext; break; }
            x0 = xn0; x1 = xn1; t0 = tn0; t1 = tn1;
            i = inext;
        }
    }
    // remainder (not taken for 8192 cols, kept for generality)
    for (; i < c4; i += P1T) {
        float4 x = lrow[i];
        int4   t = trow[i];
        float xv[4] = {x.x, x.y, x.z, x.w};
        int   tv[4] = {t.x, t.y, t.z, t.w};
        #pragma unroll
        for (int k = 0; k < 4; k++) {
            float ea  = expf(-xv[k]);
            float w1a = 1.0f + ea;
            float sa  = 1.0f / w1a;
            float ga  = tv[k] ? (1.0f - sa) : sa;
            int b = (int)(ga * 29.9999f);
            b = b < 0 ? 0 : (b > BINS - 1 ? BINS - 1 : b);
            int slot = b * P1T + tid;
            s_a[slot]  += (tv[k] ? 0.0f : xv[k]) + __logf(w1a);
            s_ca[slot] += 1;
        }
    }
    __syncthreads();

    // Cross-thread reduce: warp w handles bins w, w+4, ...
    const int warp = tid >> 5, lane = tid & 31;
    for (int b = warp; b < BINS; b += 4) {
        float        fs = 0.0f;
        unsigned int fc = 0;
        #pragma unroll
        for (int k = 0; k < 4; k++) {
            int s = b * P1T + k * 32 + lane;
            fs += s_a[s] + s_b[s];
            fc += (unsigned int)s_ca[s] + (unsigned int)s_cb[s];
        }
        #pragma unroll
        for (int off = 16; off > 0; off >>= 1) {
            fs += __shfl_down_sync(0xffffffff, fs, off);
            fc += __shfl_down_sync(0xffffffff, fc, off);
        }
        if (lane == 0) {
            g_S[b * rows + row] = fs;
            if (fc) atomicAdd(&g_cnt[b], fc);
        }
    }
}

// ---------------------------------------------------------------------------
// Finalize: beta from counts; out[row] = (1/cols) * dot(beta, S[:,row]).
// ---------------------------------------------------------------------------
__global__ void __launch_bounds__(256)
finalize_kernel(float* __restrict__ out, int rows, float inv_cols, float tot)
{
    __shared__ float beta[BINS];
    if (threadIdx.x < 32) {
        unsigned int c = (threadIdx.x < BINS) ? g_cnt[threadIdx.x] : 0u;
        unsigned int nz = __ballot_sync(0xffffffff, c > 0u);
        float nonempty = (float)__popc(nz);
        if (threadIdx.x < BINS)
            beta[threadIdx.x] = tot / fmaxf((float)c * nonempty, 1e-4f);
    }
    __syncthreads();

    int row = blockIdx.x * blockDim.x + threadIdx.x;
    if (row < rows) {
        float acc = 0.0f;
        #pragma unroll
        for (int b = 0; b < BINS; b++)
            acc += beta[b] * g_S[b * rows + row];
        out[row] = acc * inv_cols;
    }
}

// ---------------------------------------------------------------------------
extern "C" void kernel_launch(void* const* d_in, const int* in_sizes, int n_in,
                              void* d_out, int out_size)
{
    const float* logits = (const float*)d_in[0];
    const int*   target = (const int*)d_in[1];
    float*       out    = (float*)d_out;

    int n    = in_sizes[0];          // 33554432
    int rows = out_size;             // 4096
    int cols = n / rows;             // 8192
    int c4   = cols >> 2;

    // pass1 first: ncu's captured launch index (≡0 mod 3) lands on pass1.
    pass1_kernel<<<rows, P1T>>>(
        (const float4*)logits, (const int4*)target, rows, c4);
    finalize_kernel<<<(rows + 255) / 256, 256>>>(
        out, rows, 1.0f / (float)cols, (float)n);
    zero_cnt_kernel<<<1, 32>>>();
}

// round 16
// speedup vs baseline: 1.4587x; 1.4587x over previous
#include <cuda_runtime.h>
#include <cuda_bf16.h>
#include <math.h>

#define BINS 30
#define P1T 128
#define MAX_ROWS 8192

// Global scratch: per-(bin,row) BCE sums (bin-major) + global bin counts.
// g_cnt is zero at module load; zero_cnt_kernel re-zeroes it at the END of
// each call so every graph replay starts from zero.
__device__ float        g_S[BINS * MAX_ROWS];
__device__ unsigned int g_cnt[BINS];

__global__ void zero_cnt_kernel() {
    if (threadIdx.x < BINS) g_cnt[threadIdx.x] = 0u;
}

// ---------------------------------------------------------------------------
// Pass 1: one block per row, single read of logits+target.
//  - hybrid fast/exact binning (validated rel_err 6.2e-6): fast EX2/RCP
//    sigmoid; elements within 1e-3 bin-units of an edge recomputed with the
//    exact reference sequence, ONE guarded block per 8-elem batch (bitmask).
//  - bce sums: TWO per-thread float histograms -> independent 4-link
//    LDS/FADD/STS chains (R14's proven latency fix).
//  - counts: per-warp u32 smem array updated with fire-and-forget atomicAdd
//    (REDS: 1 instr/elem, NO dependency chain, no byte-RMW wavefronts).
// ---------------------------------------------------------------------------
__global__ void __launch_bounds__(P1T)
pass1_kernel(const float4* __restrict__ logits,
             const int4*  __restrict__ target,
             int rows, int c4)
{
    __shared__ float        s_a[BINS * P1T];   // 15360 B
    __shared__ float        s_b[BINS * P1T];   // 15360 B
    __shared__ unsigned int s_wc[4 * 32];      // [warp][bin], 512 B

    const int tid  = threadIdx.x;
    const int warp = tid >> 5;

    #pragma unroll
    for (int b = 0; b < BINS; b++) {
        s_a[b * P1T + tid] = 0.0f;
        s_b[b * P1T + tid] = 0.0f;
    }
    s_wc[tid] = 0u;                 // 128 threads cover all 4*32 words
    // own columns only -> no sync needed before hot loop

    unsigned int* wc = s_wc + warp * 32;

    const int row = blockIdx.x;
    const float4* lrow = logits + (size_t)row * c4;
    const int4*   trow = target + (size_t)row * c4;

    const float DELTA = 1e-3f;

    int i = tid;
    if (i + P1T < c4) {
        float4 x0 = lrow[i];
        float4 x1 = lrow[i + P1T];
        int4   t0 = trow[i];
        int4   t1 = trow[i + P1T];

        for (;;) {
            const int inext = i + 2 * P1T;
            const bool more = (inext + P1T < c4);

            float4 xn0, xn1; int4 tn0, tn1;
            if (more) {                       // prefetch next batch first
                xn0 = lrow[inext];
                xn1 = lrow[inext + P1T];
                tn0 = trow[inext];
                tn1 = trow[inext + P1T];
            }

            float xv[8] = {x0.x, x0.y, x0.z, x0.w, x1.x, x1.y, x1.z, x1.w};
            int   tv[8] = {t0.x, t0.y, t0.z, t0.w, t1.x, t1.y, t1.z, t1.w};

            int      bb[8];
            float    bc[8];
            unsigned need = 0;

            #pragma unroll
            for (int k = 0; k < 8; k++) {
                float e  = __expf(-xv[k]);           // FMUL + MUFU.EX2
                float w1 = 1.0f + e;
                float s  = __fdividef(1.0f, w1);     // MUFU.RCP
                float g  = tv[k] ? (1.0f - s) : s;
                float gb = g * 29.9999f;
                int   b  = (int)gb;
                float fr = gb - (float)b;
                need |= (fr < DELTA || fr > 1.0f - DELTA) ? (1u << k) : 0u;
                bb[k] = b;
                bc[k] = (tv[k] ? 0.0f : xv[k]) + __logf(w1);
            }

            if (need) {            // rare exact fix-up, one guard per batch
                #pragma unroll
                for (int k = 0; k < 8; k++) {
                    if ((need >> k) & 1u) {
                        float ea  = expf(-xv[k]);
                        float w1a = 1.0f + ea;
                        float sa  = 1.0f / w1a;      // IEEE division
                        float ga  = tv[k] ? (1.0f - sa) : sa;
                        bb[k] = (int)(ga * 29.9999f);
                    }
                }
            }
            #pragma unroll
            for (int k = 0; k < 8; k++) {
                int b = bb[k];
                bb[k] = b < 0 ? 0 : (b > BINS - 1 ? BINS - 1 : b);
            }

            // counts: fire-and-forget smem atomics (no chain, no return)
            #pragma unroll
            for (int k = 0; k < 8; k++)
                atomicAdd(&wc[bb[k]], 1u);

            // two independent 4-link float chains for bce sums
            #pragma unroll
            for (int k = 0; k < 4; k++) s_a[bb[k] * P1T + tid] += bc[k];
            #pragma unroll
            for (int k = 4; k < 8; k++) s_b[bb[k] * P1T + tid] += bc[k];

            if (!more) { i = inext; break; }
            x0 = xn0; x1 = xn1; t0 = tn0; t1 = tn1;
            i = inext;
        }
    }
    // remainder (not taken for 8192 cols, kept for generality)
    for (; i < c4; i += P1T) {
        float4 x = lrow[i];
        int4   t = trow[i];
        float xv[4] = {x.x, x.y, x.z, x.w};
        int   tv[4] = {t.x, t.y, t.z, t.w};
        #pragma unroll
        for (int k = 0; k < 4; k++) {
            float ea  = expf(-xv[k]);
            float w1a = 1.0f + ea;
            float sa  = 1.0f / w1a;
            float ga  = tv[k] ? (1.0f - sa) : sa;
            int b = (int)(ga * 29.9999f);
            b = b < 0 ? 0 : (b > BINS - 1 ? BINS - 1 : b);
            atomicAdd(&wc[b], 1u);
            s_a[b * P1T + tid] += (tv[k] ? 0.0f : xv[k]) + __logf(w1a);
        }
    }
    __syncthreads();

    // Cross-thread reduce of bce sums: warp w handles bins w, w+4, ...
    const int lane = tid & 31;
    for (int b = warp; b < BINS; b += 4) {
        float fs = 0.0f;
        #pragma unroll
        for (int k = 0; k < 4; k++) {
            int s = b * P1T + k * 32 + lane;
            fs += s_a[s] + s_b[s];
        }
        #pragma unroll
        for (int off = 16; off > 0; off >>= 1)
            fs += __shfl_down_sync(0xffffffff, fs, off);
        if (lane == 0)
            g_S[b * rows + row] = fs;
    }

    // Global count accumulation: 30 atomics per block.
    if (tid < BINS) {
        unsigned int c = s_wc[tid] + s_wc[32 + tid] +
                         s_wc[64 + tid] + s_wc[96 + tid];
        if (c) atomicAdd(&g_cnt[tid], c);
    }
}

// ---------------------------------------------------------------------------
// Finalize: beta from counts; out[row] = (1/cols) * dot(beta, S[:,row]).
// ---------------------------------------------------------------------------
__global__ void __launch_bounds__(256)
finalize_kernel(float* __restrict__ out, int rows, float inv_cols, float tot)
{
    __shared__ float beta[BINS];
    if (threadIdx.x < 32) {
        unsigned int c = (threadIdx.x < BINS) ? g_cnt[threadIdx.x] : 0u;
        unsigned int nz = __ballot_sync(0xffffffff, c > 0u);
        float nonempty = (float)__popc(nz);
        if (threadIdx.x < BINS)
            beta[threadIdx.x] = tot / fmaxf((float)c * nonempty, 1e-4f);
    }
    __syncthreads();

    int row = blockIdx.x * blockDim.x + threadIdx.x;
    if (row < rows) {
        float acc = 0.0f;
        #pragma unroll
        for (int b = 0; b < BINS; b++)
            acc += beta[b] * g_S[b * rows + row];
        out[row] = acc * inv_cols;
    }
}

// ---------------------------------------------------------------------------
extern "C" void kernel_launch(void* const* d_in, const int* in_sizes, int n_in,
                              void* d_out, int out_size)
{
    const float* logits = (const float*)d_in[0];
    const int*   target = (const int*)d_in[1];
    float*       out    = (float*)d_out;

    int n    = in_sizes[0];          // 33554432
    int rows = out_size;             // 4096
    int cols = n / rows;             // 8192
    int c4   = cols >> 2;

    // pass1 first: ncu's captured launch index (≡0 mod 3) lands on pass1.
    pass1_kernel<<<rows, P1T>>>(
        (const float4*)logits, (const int4*)target, rows, c4);
    finalize_kernel<<<(rows + 255) / 256, 256>>>(
        out, rows, 1.0f / (float)cols, (float)n);
    zero_cnt_kernel<<<1, 32>>>();
}